// round 10
// baseline (speedup 1.0000x reference)
#include <cuda_runtime.h>
#include <cuda_bf16.h>
#include <stdint.h>
#include <math.h>

// ---------------- global scratch (no allocations allowed) ----------------
// B fragments: [Tg=32][s=8][lane=32] uint4 {b0_hi, b1_hi, b0_lo, b1_lo}
__device__ __align__(16) uint4 g_bfr[32 * 8 * 32];
__device__ __align__(16) float g_d[256];
__device__ __align__(16) float g_c8[256];
__device__ __align__(16) float g_alpha[16];

// ---------------- helpers ----------------
#define FMA2(d, a, b) asm("fma.rn.f32x2 %0, %1, %2, %0;" : "+l"(d) : "l"(a), "l"(b))
#define DUP2(d, f)    asm("mov.b64 %0, {%1, %1};" : "=l"(d) : "f"(f))

__device__ __forceinline__ void hilo(float2 f, uint32_t& h, uint32_t& l) {
    __nv_bfloat16 ax = __float2bfloat16(f.x), ay = __float2bfloat16(f.y);
    __nv_bfloat162 hv; hv.x = ax; hv.y = ay;
    float rx = f.x - __bfloat162float(ax);
    float ry = f.y - __bfloat162float(ay);
    __nv_bfloat162 lv = __floats2bfloat162_rn(rx, ry);
    h = *reinterpret_cast<uint32_t*>(&hv);
    l = *reinterpret_cast<uint32_t*>(&lv);
}

__device__ __forceinline__ void mma16816(float* c, const uint32_t* a, uint32_t b0, uint32_t b1) {
    asm volatile(
        "mma.sync.aligned.m16n8k16.row.col.f32.bf16.bf16.f32 "
        "{%0,%1,%2,%3}, {%4,%5,%6,%7}, {%8,%9}, {%0,%1,%2,%3};\n"
        : "+f"(c[0]), "+f"(c[1]), "+f"(c[2]), "+f"(c[3])
        : "r"(a[0]), "r"(a[1]), "r"(a[2]), "r"(a[3]), "r"(b0), "r"(b1));
}

// ================= kernel 1: merged prep (M^T + fragments + d + c8 + alpha) =================
// grid 33, 512 threads. CTA b<32: n-group n0=b*8, FULL K=512.
//   thread: o = tid>>2 (0..127); q = tid&3 -> tx = q&1 (n quad), kh = q>>1 (k half of 256).
//   A row chunk (64 floats) in registers; foldW staged once in smem; FFMA2 inner loop.
//   In-CTA reduction over kh -> sMt[n][o] -> bf16 hi/lo fragments -> g_bfr (same layout as before).
// CTA b==32: alpha LUT + c8.
__global__ __launch_bounds__(512) void prep(const float* __restrict__ A,     // pre_fc_w (128,512)
                                            const float* __restrict__ bias,  // pre_fc_b (512,)
                                            const float* __restrict__ vw,    // value_w (512,1024)
                                            const float* __restrict__ pw,    // p_w (16,64)
                                            const float* __restrict__ pb,    // p_b (64,)
                                            const float* __restrict__ vb) {  // value_b (1024,)
    int b = blockIdx.x, tid = threadIdx.x;

    if (b == 32) {
        __shared__ float s16[16 * 64];
        if (tid < 256) {
            float c = 0.25f * (vb[tid] + vb[tid + 256] + vb[tid + 512] + vb[tid + 768]);
            g_c8[tid] = 0.125f * c;
        }
        for (int i = tid; i < 16 * 64; i += 512) s16[i] = pw[i] + pb[i & 63];
        __syncthreads();
        if (tid < 16) {
            float* s = s16 + tid * 64;
            float S = 0.f;
            for (int t8 = 0; t8 < 8; t8++) {
                float bv = -1e30f; int bi = 0;
                for (int n = 0; n < 64; n++) {
                    float v = s[n];
                    if (v > bv) { bv = v; bi = n; }
                }
                S += 1.f / (1.f + expf(-bv));   // softmax([x,0])[0] = sigmoid(x)
                s[bi] = -1e30f;
            }
            g_alpha[tid] = S * (1.0f / 64.0f);
        }
        return;
    }

    __shared__ __align__(16) float sW[512 * 8];      // [k][8n] foldW, 16 KB
    __shared__ __align__(16) float sP[2][128][8];    // kh partials, 8 KB
    __shared__ __align__(16) float sPb[2][8];        // bias kh partials
    __shared__ __align__(16) float sMt[8 * 132];     // reduced M^T [n][o]
    int n0 = b * 8;

    // stage foldW (512 k x 8 n), head-mean folded
    #pragma unroll
    for (int i = 0; i < 8; i++) {
        int id = i * 512 + tid;
        int k = id >> 3, n = id & 7;
        const float* p = vw + (size_t)k * 1024 + n0 + n;
        sW[id] = 0.25f * (p[0] + p[256] + p[512] + p[768]);
    }
    __syncthreads();

    int o = tid >> 2, q = tid & 3;
    int tx = q & 1, kh = q >> 1;
    const float4* ar = (const float4*)(A + (size_t)o * 512 + kh * 256);

    unsigned long long acc0 = 0ull, acc1 = 0ull;     // f32x2 accumulators (4 n)
    #pragma unroll
    for (int c = 0; c < 4; c++) {
        float4 a4[16];                               // 64 consecutive k in regs
        #pragma unroll
        for (int i = 0; i < 16; i++) a4[i] = ar[c * 16 + i];
        const float* sw = &sW[(kh * 256 + c * 64) * 8 + tx * 4];
        #pragma unroll
        for (int k = 0; k < 64; k++) {
            ulonglong2 bp = *(const ulonglong2*)(sw + k * 8);
            unsigned long long ad; DUP2(ad, ((const float*)a4)[k]);
            FMA2(acc0, ad, bp.x);
            FMA2(acc1, ad, bp.y);
        }
    }
    *(unsigned long long*)&sP[kh][o][tx * 4]     = acc0;
    *(unsigned long long*)&sP[kh][o][tx * 4 + 2] = acc1;

    // bias row: threads 0..3 only (warp-0 tail)
    if (tid < 4) {
        int btx = tid & 1, bkh = tid >> 1;
        const float4* br = (const float4*)(bias + bkh * 256);
        unsigned long long bacc0 = 0ull, bacc1 = 0ull;
        #pragma unroll
        for (int c = 0; c < 4; c++) {
            float4 a4[16];
            #pragma unroll
            for (int i = 0; i < 16; i++) a4[i] = br[c * 16 + i];
            const float* sw = &sW[(bkh * 256 + c * 64) * 8 + btx * 4];
            #pragma unroll
            for (int k = 0; k < 64; k++) {
                ulonglong2 bp = *(const ulonglong2*)(sw + k * 8);
                unsigned long long ad; DUP2(ad, ((const float*)a4)[k]);
                FMA2(bacc0, ad, bp.x);
                FMA2(bacc1, ad, bp.y);
            }
        }
        *(unsigned long long*)&sPb[bkh][btx * 4]     = bacc0;
        *(unsigned long long*)&sPb[bkh][btx * 4 + 2] = bacc1;
    }
    __syncthreads();

    // reduce kh and transpose into sMt[n][o]
    if (tid < 128) {
        float4 p00 = *(const float4*)&sP[0][tid][0];
        float4 p01 = *(const float4*)&sP[0][tid][4];
        float4 p10 = *(const float4*)&sP[1][tid][0];
        float4 p11 = *(const float4*)&sP[1][tid][4];
        sMt[0 * 132 + tid] = p00.x + p10.x;
        sMt[1 * 132 + tid] = p00.y + p10.y;
        sMt[2 * 132 + tid] = p00.z + p10.z;
        sMt[3 * 132 + tid] = p00.w + p10.w;
        sMt[4 * 132 + tid] = p01.x + p11.x;
        sMt[5 * 132 + tid] = p01.y + p11.y;
        sMt[6 * 132 + tid] = p01.z + p11.z;
        sMt[7 * 132 + tid] = p01.w + p11.w;
    } else if (tid < 136) {
        int n = tid - 128;
        g_d[n0 + n] = sPb[0][n] + sPb[1][n];
    }
    __syncthreads();

    // pack fragments for Tg = b (identical layout to previous pack kernel)
    if (tid < 256) {
        int lane = tid & 31, s = tid >> 5;
        int nl = lane >> 2;
        int o0 = s * 16 + (lane & 3) * 2;
        const float* row = &sMt[nl * 132];
        float2 f0 = { row[o0],     row[o0 + 1] };
        float2 f1 = { row[o0 + 8], row[o0 + 9] };
        uint4 qv; uint32_t l0, l1;
        hilo(f0, qv.x, l0); hilo(f1, qv.y, l1);
        qv.z = l0; qv.w = l1;
        g_bfr[b * 256 + tid] = qv;
    }
}

// ================= kernel 2: main HMMA GEMM + coalesced epilogue =================
// CTA tile 64m x 128n; grid (128, 2); 8 warps = 2(wm) x 4(wn); 3 CTAs/SM.
static constexpr int MO_AH  = 0;        // uint4[1024] = 16384 (A hi) ── overlaid with EPI
static constexpr int MO_AL  = 16384;    // uint4[1024] = 16384 (A lo) ──┘
static constexpr int MO_EPI = 0;        // float[64][132] = 33792 (post-mma scratch)
static constexpr int MO_DS  = 33792;    // float[128]
static constexpr int MO_C8  = 34304;    // float[128]
static constexpr int MO_ALS = 34816;    // float[64]
static constexpr int MSMEM  = 35072;

__global__ __launch_bounds__(256, 3) void main_hmma(const float* __restrict__ x,   // (8192,128)
                                                    const int* __restrict__ opt,   // (8192,)
                                                    float* __restrict__ out) {     // (8192,256)
    extern __shared__ __align__(16) char sm[];
    uint4* ah_s = (uint4*)(sm + MO_AH);
    uint4* al_s = (uint4*)(sm + MO_AL);
    float* epi  = (float*)(sm + MO_EPI);
    float* ds   = (float*)(sm + MO_DS);
    float* c8s  = (float*)(sm + MO_C8);
    float* als  = (float*)(sm + MO_ALS);

    int tid = threadIdx.x;
    int m0 = blockIdx.x * 64;
    int nt = blockIdx.y, n0 = nt * 128;

    if (tid < 128) { ds[tid] = g_d[n0 + tid]; c8s[tid] = g_c8[n0 + tid]; }
    if (tid < 64)  als[tid] = g_alpha[opt[m0 + tid]];

    // stage A fragments (hi/lo separate, lane-contiguous)
    #pragma unroll
    for (int i = 0; i < 4; i++) {
        int p = tid + i * 256;
        int lane_ = p & 31, s = (p >> 5) & 7, mf = p >> 8;
        int row = m0 + mf * 16 + (lane_ >> 2);
        int k0 = s * 16 + (lane_ & 3) * 2;
        const float* xr = x + (size_t)row * 128;
        float2 xa = *(const float2*)(xr + k0);
        float2 xb = *(const float2*)(xr + 8 * 128 + k0);
        float2 xc = *(const float2*)(xr + k0 + 8);
        float2 xd = *(const float2*)(xr + 8 * 128 + k0 + 8);
        uint4 hi, lo;
        hilo(xa, hi.x, lo.x); hilo(xb, hi.y, lo.y);
        hilo(xc, hi.z, lo.z); hilo(xd, hi.w, lo.w);
        ah_s[p] = hi;
        al_s[p] = lo;
    }
    __syncthreads();

    int wid = tid >> 5, lane = tid & 31;
    int wm = wid & 1, wn = wid >> 1;
    const uint4* bg = g_bfr + nt * 4096 + (wn * 4) * 256 + lane;  // t stride 256, s stride 32

    float acc[2][4][4];
    #pragma unroll
    for (int a_ = 0; a_ < 2; a_++)
        #pragma unroll
        for (int b_ = 0; b_ < 4; b_++)
            #pragma unroll
            for (int c_ = 0; c_ < 4; c_++) acc[a_][b_][c_] = 0.f;

    #pragma unroll
    for (int s = 0; s < 8; s++) {
        uint4 bq0 = bg[0 * 256 + s * 32];
        uint4 bq1 = bg[1 * 256 + s * 32];
        uint4 bq2 = bg[2 * 256 + s * 32];
        uint4 bq3 = bg[3 * 256 + s * 32];
        uint4 ah[2], al[2];
        #pragma unroll
        for (int mt = 0; mt < 2; mt++) {
            int fp = ((wm * 2 + mt) * 8 + s) * 32 + lane;
            ah[mt] = ah_s[fp];
            al[mt] = al_s[fp];
        }
        #pragma unroll
        for (int mt = 0; mt < 2; mt++) {
            mma16816(acc[mt][0], (const uint32_t*)&ah[mt], bq0.x, bq0.y);
            mma16816(acc[mt][0], (const uint32_t*)&ah[mt], bq0.z, bq0.w);
            mma16816(acc[mt][0], (const uint32_t*)&al[mt], bq0.x, bq0.y);
            mma16816(acc[mt][1], (const uint32_t*)&ah[mt], bq1.x, bq1.y);
            mma16816(acc[mt][1], (const uint32_t*)&ah[mt], bq1.z, bq1.w);
            mma16816(acc[mt][1], (const uint32_t*)&al[mt], bq1.x, bq1.y);
            mma16816(acc[mt][2], (const uint32_t*)&ah[mt], bq2.x, bq2.y);
            mma16816(acc[mt][2], (const uint32_t*)&ah[mt], bq2.z, bq2.w);
            mma16816(acc[mt][2], (const uint32_t*)&al[mt], bq2.x, bq2.y);
            mma16816(acc[mt][3], (const uint32_t*)&ah[mt], bq3.x, bq3.y);
            mma16816(acc[mt][3], (const uint32_t*)&ah[mt], bq3.z, bq3.w);
            mma16816(acc[mt][3], (const uint32_t*)&al[mt], bq3.x, bq3.y);
        }
    }

    // --- epilogue: raw accs -> smem (overwrites A frags), coalesced read-back ---
    __syncthreads();
    int g = lane >> 2, tq = lane & 3;
    #pragma unroll
    for (int mt = 0; mt < 2; mt++) {
        int rl = wm * 32 + mt * 16 + g;
        #pragma unroll
        for (int t = 0; t < 4; t++) {
            int nl = wn * 32 + t * 8 + tq * 2;
            float* c = acc[mt][t];
            *(float2*)&epi[rl * 132 + nl]       = make_float2(c[0], c[1]);
            *(float2*)&epi[(rl + 8) * 132 + nl] = make_float2(c[2], c[3]);
        }
    }
    float4 dd = *(const float4*)&ds[lane * 4];
    float4 cc = *(const float4*)&c8s[lane * 4];
    __syncthreads();

    #pragma unroll
    for (int it = 0; it < 8; it++) {
        int row = wid * 8 + it;
        float a = als[row];
        float4 v = *(const float4*)&epi[row * 132 + lane * 4];
        float4 o;
        o.x = fmaf(v.x + dd.x, a, cc.x);
        o.y = fmaf(v.y + dd.y, a, cc.y);
        o.z = fmaf(v.z + dd.z, a, cc.z);
        o.w = fmaf(v.w + dd.w, a, cc.w);
        *(float4*)&out[(size_t)(m0 + row) * 256 + n0 + lane * 4] = o;
    }
}

extern "C" void kernel_launch(void* const* d_in, const int* in_sizes, int n_in,
                              void* d_out, int out_size) {
    const float* x        = (const float*)d_in[0];   // (8192,128)
    const int*   option   = (const int*)  d_in[1];   // (8192,)
    const float* pre_fc_w = (const float*)d_in[2];   // (128,512)
    const float* pre_fc_b = (const float*)d_in[3];   // (512,)
    const float* value_w  = (const float*)d_in[4];   // (512,1024)
    const float* value_b  = (const float*)d_in[5];   // (1024,)
    const float* p_w      = (const float*)d_in[6];   // (16,64)
    const float* p_b      = (const float*)d_in[7];   // (64,)
    float* out = (float*)d_out;                      // (8192,256)

    prep<<<33, 512>>>(pre_fc_w, pre_fc_b, value_w, p_w, p_b, value_b);
    main_hmma<<<dim3(128, 2), 256, MSMEM>>>(x, option, out);
}

// round 11
// speedup vs baseline: 1.7181x; 1.7181x over previous
#include <cuda_runtime.h>
#include <cuda_bf16.h>
#include <stdint.h>
#include <math.h>

// ---------------- global scratch (no allocations allowed) ----------------
// split-K partials: [ks=16][n=256][o stride 132] (o: 0..127 = M^T, 128 = d)
__device__ __align__(16) float g_part[16 * 256 * 132];
// B fragments: [Tg=32][s=8][lane=32] uint4 {b0_hi, b1_hi, b0_lo, b1_lo}
__device__ __align__(16) uint4 g_bfr[32 * 8 * 32];
__device__ __align__(16) float g_d[256];
__device__ __align__(16) float g_c8[256];
__device__ __align__(16) float g_alpha[16];

// ---------------- helpers ----------------
__device__ __forceinline__ void hilo(float2 f, uint32_t& h, uint32_t& l) {
    __nv_bfloat16 ax = __float2bfloat16(f.x), ay = __float2bfloat16(f.y);
    __nv_bfloat162 hv; hv.x = ax; hv.y = ay;
    float rx = f.x - __bfloat162float(ax);
    float ry = f.y - __bfloat162float(ay);
    __nv_bfloat162 lv = __floats2bfloat162_rn(rx, ry);
    h = *reinterpret_cast<uint32_t*>(&hv);
    l = *reinterpret_cast<uint32_t*>(&lv);
}

__device__ __forceinline__ void mma16816(float* c, const uint32_t* a, uint32_t b0, uint32_t b1) {
    asm volatile(
        "mma.sync.aligned.m16n8k16.row.col.f32.bf16.bf16.f32 "
        "{%0,%1,%2,%3}, {%4,%5,%6,%7}, {%8,%9}, {%0,%1,%2,%3};\n"
        : "+f"(c[0]), "+f"(c[1]), "+f"(c[2]), "+f"(c[3])
        : "r"(a[0]), "r"(a[1]), "r"(a[2]), "r"(a[3]), "r"(b0), "r"(b1));
}

// ================= kernel 1: split-K partial GEMM (16 n x 32 k per CTA) =================
// (R8 version, measured 7.2us — do not "improve")
__global__ __launch_bounds__(256) void prep1(const float* __restrict__ A,     // pre_fc_w (128,512)
                                             const float* __restrict__ bias,  // pre_fc_b (512,)
                                             const float* __restrict__ vw) {  // value_w (512,1024)
    __shared__ __align__(16) float sA[129 * 36];   // [o][k], LD=36
    __shared__ __align__(16) float sB[32 * 16];    // [k][n]
    int tid = threadIdx.x;
    int nt = blockIdx.x, ks = blockIdx.y;
    int n0 = nt * 16, k0 = ks * 32;

    #pragma unroll
    for (int i = 0; i < 5; i++) {
        int fid = tid + i * 256;
        if (fid < 129 * 8) {
            int row = fid >> 3, kq = fid & 7;
            float4 v = (row < 128) ? *(const float4*)(A + (size_t)row * 512 + k0 + kq * 4)
                                   : *(const float4*)(bias + k0 + kq * 4);
            *(float4*)(sA + row * 36 + kq * 4) = v;
        }
    }
    #pragma unroll
    for (int i = 0; i < 2; i++) {
        int idx = tid + i * 256;
        int k = idx >> 4, j = idx & 15;
        const float* p = vw + (size_t)(k0 + k) * 1024 + n0 + j;
        sB[k * 16 + j] = 0.25f * (p[0] + p[256] + p[512] + p[768]);
    }
    __syncthreads();

    int tx = tid & 3, ty = tid >> 2;
    float acc0[4] = {}, acc1[4] = {}, accb[4] = {};
    #pragma unroll
    for (int k = 0; k < 32; k++) {
        float4 b4 = *(const float4*)&sB[k * 16 + tx * 4];
        float a0 = sA[ty * 36 + k];
        float a1 = sA[(ty + 64) * 36 + k];
        acc0[0] = fmaf(a0, b4.x, acc0[0]); acc0[1] = fmaf(a0, b4.y, acc0[1]);
        acc0[2] = fmaf(a0, b4.z, acc0[2]); acc0[3] = fmaf(a0, b4.w, acc0[3]);
        acc1[0] = fmaf(a1, b4.x, acc1[0]); acc1[1] = fmaf(a1, b4.y, acc1[1]);
        acc1[2] = fmaf(a1, b4.z, acc1[2]); acc1[3] = fmaf(a1, b4.w, acc1[3]);
        if (ty == 0) {
            float ab = sA[128 * 36 + k];
            accb[0] = fmaf(ab, b4.x, accb[0]); accb[1] = fmaf(ab, b4.y, accb[1]);
            accb[2] = fmaf(ab, b4.z, accb[2]); accb[3] = fmaf(ab, b4.w, accb[3]);
        }
    }
    #pragma unroll
    for (int j = 0; j < 4; j++) {
        size_t base = ((size_t)ks * 256 + n0 + tx * 4 + j) * 132;
        g_part[base + ty]      = acc0[j];
        g_part[base + ty + 64] = acc1[j];
        if (ty == 0) g_part[base + 128] = accb[j];
    }
}

// ================= kernel 2: pack fragments + d + c8 + alpha =================
__global__ __launch_bounds__(256) void pack(const float* __restrict__ pw,   // p_w (16,64)
                                            const float* __restrict__ pb,   // p_b (64,)
                                            const float* __restrict__ vb) { // value_b (1024,)
    int b = blockIdx.x, tid = threadIdx.x;
    if (b < 32) {
        int p = b * 256 + tid;                 // == (Tg*8+s)*32+lane
        int lane = p & 31, s = (p >> 5) & 7;
        int n = (p >> 8) * 8 + (lane >> 2);
        int o0 = s * 16 + (lane & 3) * 2;
        float2 f0 = {0.f, 0.f}, f1 = {0.f, 0.f};
        #pragma unroll
        for (int ks = 0; ks < 16; ks++) {
            const float* q = &g_part[((size_t)ks * 256 + n) * 132];
            float2 u = *(const float2*)(q + o0);
            float2 v = *(const float2*)(q + o0 + 8);
            f0.x += u.x; f0.y += u.y; f1.x += v.x; f1.y += v.y;
        }
        uint4 qv; uint32_t l0, l1;
        hilo(f0, qv.x, l0); hilo(f1, qv.y, l1);
        qv.z = l0; qv.w = l1;
        g_bfr[p] = qv;
    } else {
        float d = 0.f;
        #pragma unroll
        for (int ks = 0; ks < 16; ks++)
            d += g_part[((size_t)ks * 256 + tid) * 132 + 128];
        g_d[tid] = d;
        float c = 0.25f * (vb[tid] + vb[tid + 256] + vb[tid + 512] + vb[tid + 768]);
        g_c8[tid] = 0.125f * c;
        __shared__ float s16[16 * 64];
        for (int i = tid; i < 16 * 64; i += 256) s16[i] = pw[i] + pb[i & 63];
        __syncthreads();
        if (tid < 16) {
            float* s = s16 + tid * 64;
            float S = 0.f;
            for (int t8 = 0; t8 < 8; t8++) {
                float bv = -1e30f; int bi = 0;
                for (int n = 0; n < 64; n++) {
                    float v = s[n];
                    if (v > bv) { bv = v; bi = n; }
                }
                S += 1.f / (1.f + expf(-bv));   // softmax([x,0])[0] = sigmoid(x)
                s[bi] = -1e30f;
            }
            g_alpha[tid] = S * (1.0f / 64.0f);
        }
    }
}

// ================= kernel 3: main HMMA GEMM, 64m x 64n tiles =================
// grid (128, 4) = 512 CTAs (~3.5/SM -> latency actually hidden). 8 warps = 2(wm) x 4(wn),
// each warp: 2 m-frags x 2 Tg-tiles. B via LDG (L2-hot), A fragments in smem,
// coalesced epilogue through smem.
static constexpr int MO_AH  = 0;        // uint4[1024] = 16384 (A hi) ── overlaid with EPI
static constexpr int MO_AL  = 16384;    // uint4[1024] = 16384 (A lo) ──┘
static constexpr int MO_EPI = 0;        // float[64][68] = 17408 (post-mma scratch)
static constexpr int MO_DS  = 32768;    // float[64]
static constexpr int MO_C8  = 33024;    // float[64]
static constexpr int MO_ALS = 33280;    // float[64]
static constexpr int MSMEM  = 33536;

__global__ __launch_bounds__(256, 3) void main_hmma(const float* __restrict__ x,   // (8192,128)
                                                    const int* __restrict__ opt,   // (8192,)
                                                    float* __restrict__ out) {     // (8192,256)
    extern __shared__ __align__(16) char sm[];
    uint4* ah_s = (uint4*)(sm + MO_AH);
    uint4* al_s = (uint4*)(sm + MO_AL);
    float* epi  = (float*)(sm + MO_EPI);
    float* ds   = (float*)(sm + MO_DS);
    float* c8s  = (float*)(sm + MO_C8);
    float* als  = (float*)(sm + MO_ALS);

    int tid = threadIdx.x;
    int m0 = blockIdx.x * 64;
    int ny = blockIdx.y, n0 = ny * 64;

    if (tid < 64) {
        ds[tid]  = g_d[n0 + tid];
        c8s[tid] = g_c8[n0 + tid];
        als[tid] = g_alpha[opt[m0 + tid]];
    }

    // stage A fragments (hi/lo separate, lane-contiguous)
    #pragma unroll
    for (int i = 0; i < 4; i++) {
        int p = tid + i * 256;
        int lane_ = p & 31, s = (p >> 5) & 7, mf = p >> 8;
        int row = m0 + mf * 16 + (lane_ >> 2);
        int k0 = s * 16 + (lane_ & 3) * 2;
        const float* xr = x + (size_t)row * 128;
        float2 xa = *(const float2*)(xr + k0);
        float2 xb = *(const float2*)(xr + 8 * 128 + k0);
        float2 xc = *(const float2*)(xr + k0 + 8);
        float2 xd = *(const float2*)(xr + 8 * 128 + k0 + 8);
        uint4 hi, lo;
        hilo(xa, hi.x, lo.x); hilo(xb, hi.y, lo.y);
        hilo(xc, hi.z, lo.z); hilo(xd, hi.w, lo.w);
        ah_s[p] = hi;
        al_s[p] = lo;
    }
    __syncthreads();

    int wid = tid >> 5, lane = tid & 31;
    int wm = wid & 1, wn = wid >> 1;           // wm: 32 rows, wn: 16 cols (2 Tg)
    // Tg for this warp: ny*8 + wn*2 + t, t in {0,1}
    const uint4* bg = g_bfr + ((ny * 8 + wn * 2) * 8) * 32 + lane;  // t stride 8*32, s stride 32

    float acc[2][2][4];
    #pragma unroll
    for (int a_ = 0; a_ < 2; a_++)
        #pragma unroll
        for (int b_ = 0; b_ < 2; b_++)
            #pragma unroll
            for (int c_ = 0; c_ < 4; c_++) acc[a_][b_][c_] = 0.f;

    #pragma unroll
    for (int s = 0; s < 8; s++) {
        uint4 bq0 = bg[0 * 256 + s * 32];
        uint4 bq1 = bg[1 * 256 + s * 32];
        uint4 ah[2], al[2];
        #pragma unroll
        for (int mt = 0; mt < 2; mt++) {
            int fp = ((wm * 2 + mt) * 8 + s) * 32 + lane;
            ah[mt] = ah_s[fp];
            al[mt] = al_s[fp];
        }
        #pragma unroll
        for (int mt = 0; mt < 2; mt++) {
            mma16816(acc[mt][0], (const uint32_t*)&ah[mt], bq0.x, bq0.y);
            mma16816(acc[mt][0], (const uint32_t*)&ah[mt], bq0.z, bq0.w);
            mma16816(acc[mt][0], (const uint32_t*)&al[mt], bq0.x, bq0.y);
            mma16816(acc[mt][1], (const uint32_t*)&ah[mt], bq1.x, bq1.y);
            mma16816(acc[mt][1], (const uint32_t*)&ah[mt], bq1.z, bq1.w);
            mma16816(acc[mt][1], (const uint32_t*)&al[mt], bq1.x, bq1.y);
        }
    }

    // --- epilogue: raw accs -> smem (overwrites A frags), coalesced read-back ---
    __syncthreads();
    int g = lane >> 2, tq = lane & 3;
    #pragma unroll
    for (int mt = 0; mt < 2; mt++) {
        int rl = wm * 32 + mt * 16 + g;
        #pragma unroll
        for (int t = 0; t < 2; t++) {
            int nl = wn * 16 + t * 8 + tq * 2;
            float* c = acc[mt][t];
            *(float2*)&epi[rl * 68 + nl]       = make_float2(c[0], c[1]);
            *(float2*)&epi[(rl + 8) * 68 + nl] = make_float2(c[2], c[3]);
        }
    }
    float2 dd = *(const float2*)&ds[lane * 2];
    float2 cc = *(const float2*)&c8s[lane * 2];
    __syncthreads();

    #pragma unroll
    for (int it = 0; it < 8; it++) {
        int row = wid * 8 + it;
        float a = als[row];
        float2 v = *(const float2*)&epi[row * 68 + lane * 2];
        float2 o;
        o.x = fmaf(v.x + dd.x, a, cc.x);
        o.y = fmaf(v.y + dd.y, a, cc.y);
        *(float2*)&out[(size_t)(m0 + row) * 256 + n0 + lane * 2] = o;
    }
}

extern "C" void kernel_launch(void* const* d_in, const int* in_sizes, int n_in,
                              void* d_out, int out_size) {
    const float* x        = (const float*)d_in[0];   // (8192,128)
    const int*   option   = (const int*)  d_in[1];   // (8192,)
    const float* pre_fc_w = (const float*)d_in[2];   // (128,512)
    const float* pre_fc_b = (const float*)d_in[3];   // (512,)
    const float* value_w  = (const float*)d_in[4];   // (512,1024)
    const float* value_b  = (const float*)d_in[5];   // (1024,)
    const float* p_w      = (const float*)d_in[6];   // (16,64)
    const float* p_b      = (const float*)d_in[7];   // (64,)
    float* out = (float*)d_out;                      // (8192,256)

    prep1<<<dim3(16, 16), 256>>>(pre_fc_w, pre_fc_b, value_w);
    pack<<<33, 256>>>(p_w, p_b, value_b);
    main_hmma<<<dim3(128, 4), 256, MSMEM>>>(x, option, out);
}

// round 12
// speedup vs baseline: 1.8901x; 1.1001x over previous
#include <cuda_runtime.h>
#include <cuda_bf16.h>
#include <stdint.h>
#include <math.h>

// ---------------- global scratch (no allocations allowed) ----------------
// split-K partials: [ks=16][n=256][o stride 132] (o: 0..127 = M^T, 128 = d)
__device__ __align__(16) float g_part[16 * 256 * 132];
// B fragments: [Tg=32][s=8][lane=32] uint4 {b0_hi, b1_hi, b0_lo, b1_lo}
__device__ __align__(16) uint4 g_bfr[32 * 8 * 32];
__device__ __align__(16) float g_d[256];
__device__ __align__(16) float g_c8[256];
__device__ __align__(16) float g_alpha[16];
__device__ unsigned g_cnt16[16] = {};   // per-n-group arrival counters (reset each launch)

// ---------------- helpers ----------------
__device__ __forceinline__ void hilo(float2 f, uint32_t& h, uint32_t& l) {
    __nv_bfloat16 ax = __float2bfloat16(f.x), ay = __float2bfloat16(f.y);
    __nv_bfloat162 hv; hv.x = ax; hv.y = ay;
    float rx = f.x - __bfloat162float(ax);
    float ry = f.y - __bfloat162float(ay);
    __nv_bfloat162 lv = __floats2bfloat162_rn(rx, ry);
    h = *reinterpret_cast<uint32_t*>(&hv);
    l = *reinterpret_cast<uint32_t*>(&lv);
}

__device__ __forceinline__ void mma16816(float* c, const uint32_t* a, uint32_t b0, uint32_t b1) {
    asm volatile(
        "mma.sync.aligned.m16n8k16.row.col.f32.bf16.bf16.f32 "
        "{%0,%1,%2,%3}, {%4,%5,%6,%7}, {%8,%9}, {%0,%1,%2,%3};\n"
        : "+f"(c[0]), "+f"(c[1]), "+f"(c[2]), "+f"(c[3])
        : "r"(a[0]), "r"(a[1]), "r"(a[2]), "r"(a[3]), "r"(b0), "r"(b1));
}

// ================= kernel 1: split-K partial GEMM + fused last-CTA pack =================
// grid (17,16). Blocks (nt<16, ks): R8 prep1 core (16 n x 32 k, measured 7.2us — hot path
// untouched), then threadfence-reduction: the 16th finisher for column-group nt packs the
// final bf16 fragments + d for that group. Block (16,0): alpha LUT + c8. (16,y>0): exit.
__global__ __launch_bounds__(256) void prep1(const float* __restrict__ A,     // pre_fc_w (128,512)
                                             const float* __restrict__ bias,  // pre_fc_b (512,)
                                             const float* __restrict__ vw,    // value_w (512,1024)
                                             const float* __restrict__ pw,    // p_w (16,64)
                                             const float* __restrict__ pb,    // p_b (64,)
                                             const float* __restrict__ vb) {  // value_b (1024,)
    int tid = threadIdx.x;
    int nt = blockIdx.x, ks = blockIdx.y;

    if (nt == 16) {
        if (ks != 0) return;
        // alpha LUT + c8
        float c = 0.25f * (vb[tid] + vb[tid + 256] + vb[tid + 512] + vb[tid + 768]);
        g_c8[tid] = 0.125f * c;
        __shared__ float s16[16 * 64];
        for (int i = tid; i < 16 * 64; i += 256) s16[i] = pw[i] + pb[i & 63];
        __syncthreads();
        if (tid < 16) {
            float* s = s16 + tid * 64;
            float S = 0.f;
            for (int t8 = 0; t8 < 8; t8++) {
                float bv = -1e30f; int bi = 0;
                for (int n = 0; n < 64; n++) {
                    float v = s[n];
                    if (v > bv) { bv = v; bi = n; }
                }
                S += 1.f / (1.f + expf(-bv));   // softmax([x,0])[0] = sigmoid(x)
                s[bi] = -1e30f;
            }
            g_alpha[tid] = S * (1.0f / 64.0f);
        }
        return;
    }

    __shared__ __align__(16) float sA[129 * 36];   // [o][k], LD=36
    __shared__ __align__(16) float sB[32 * 16];    // [k][n]
    int n0 = nt * 16, k0 = ks * 32;

    #pragma unroll
    for (int i = 0; i < 5; i++) {
        int fid = tid + i * 256;
        if (fid < 129 * 8) {
            int row = fid >> 3, kq = fid & 7;
            float4 v = (row < 128) ? *(const float4*)(A + (size_t)row * 512 + k0 + kq * 4)
                                   : *(const float4*)(bias + k0 + kq * 4);
            *(float4*)(sA + row * 36 + kq * 4) = v;
        }
    }
    #pragma unroll
    for (int i = 0; i < 2; i++) {
        int idx = tid + i * 256;
        int k = idx >> 4, j = idx & 15;
        const float* p = vw + (size_t)(k0 + k) * 1024 + n0 + j;
        sB[k * 16 + j] = 0.25f * (p[0] + p[256] + p[512] + p[768]);
    }
    __syncthreads();

    int tx = tid & 3, ty = tid >> 2;
    float acc0[4] = {}, acc1[4] = {}, accb[4] = {};
    #pragma unroll
    for (int k = 0; k < 32; k++) {
        float4 b4 = *(const float4*)&sB[k * 16 + tx * 4];
        float a0 = sA[ty * 36 + k];
        float a1 = sA[(ty + 64) * 36 + k];
        acc0[0] = fmaf(a0, b4.x, acc0[0]); acc0[1] = fmaf(a0, b4.y, acc0[1]);
        acc0[2] = fmaf(a0, b4.z, acc0[2]); acc0[3] = fmaf(a0, b4.w, acc0[3]);
        acc1[0] = fmaf(a1, b4.x, acc1[0]); acc1[1] = fmaf(a1, b4.y, acc1[1]);
        acc1[2] = fmaf(a1, b4.z, acc1[2]); acc1[3] = fmaf(a1, b4.w, acc1[3]);
        if (ty == 0) {
            float ab = sA[128 * 36 + k];
            accb[0] = fmaf(ab, b4.x, accb[0]); accb[1] = fmaf(ab, b4.y, accb[1]);
            accb[2] = fmaf(ab, b4.z, accb[2]); accb[3] = fmaf(ab, b4.w, accb[3]);
        }
    }
    #pragma unroll
    for (int j = 0; j < 4; j++) {
        size_t base = ((size_t)ks * 256 + n0 + tx * 4 + j) * 132;
        g_part[base + ty]      = acc0[j];
        g_part[base + ty + 64] = acc1[j];
        if (ty == 0) g_part[base + 128] = accb[j];
    }

    // ---- last-CTA-done pack for column group nt (threadfence-reduction pattern) ----
    __threadfence();
    __syncthreads();
    __shared__ unsigned s_last;
    if (tid == 0) s_last = (atomicAdd(&g_cnt16[nt], 1u) == 15u) ? 1u : 0u;
    __syncthreads();
    if (!s_last) return;
    if (tid == 0) atomicExch(&g_cnt16[nt], 0u);    // reset for next launch (replay-safe)

    // fragments for Tg = nt*2, nt*2+1  (512 uint4; 2 per thread)
    #pragma unroll
    for (int e = 0; e < 2; e++) {
        int p = nt * 512 + e * 256 + tid;          // == (Tg*8+s)*32+lane
        int lane = p & 31, s = (p >> 5) & 7;
        int n = (p >> 8) * 8 + (lane >> 2);
        int o0 = s * 16 + (lane & 3) * 2;
        float2 f0 = {0.f, 0.f}, f1 = {0.f, 0.f};
        #pragma unroll
        for (int kk = 0; kk < 16; kk++) {
            const float* q = &g_part[((size_t)kk * 256 + n) * 132];
            float2 u = __ldcg((const float2*)(q + o0));
            float2 v = __ldcg((const float2*)(q + o0 + 8));
            f0.x += u.x; f0.y += u.y; f1.x += v.x; f1.y += v.y;
        }
        uint4 qv; uint32_t l0, l1;
        hilo(f0, qv.x, l0); hilo(f1, qv.y, l1);
        qv.z = l0; qv.w = l1;
        g_bfr[p] = qv;
    }
    // d for this n-group
    if (tid < 16) {
        int n = n0 + tid;
        float d = 0.f;
        #pragma unroll
        for (int kk = 0; kk < 16; kk++)
            d += __ldcg(&g_part[((size_t)kk * 256 + n) * 132 + 128]);
        g_d[n] = d;
    }
}

// ================= kernel 2: main HMMA GEMM (R8-proven config, unchanged) =================
// CTA tile 64m x 128n; grid (128, 2); 8 warps = 2(wm) x 4(wn); 3 CTAs/SM.
static constexpr int MO_AH  = 0;        // uint4[1024] = 16384 (A hi) ── overlaid with EPI
static constexpr int MO_AL  = 16384;    // uint4[1024] = 16384 (A lo) ──┘
static constexpr int MO_EPI = 0;        // float[64][132] = 33792 (post-mma scratch)
static constexpr int MO_DS  = 33792;    // float[128]
static constexpr int MO_C8  = 34304;    // float[128]
static constexpr int MO_ALS = 34816;    // float[64]
static constexpr int MSMEM  = 35072;

__global__ __launch_bounds__(256, 3) void main_hmma(const float* __restrict__ x,   // (8192,128)
                                                    const int* __restrict__ opt,   // (8192,)
                                                    float* __restrict__ out) {     // (8192,256)
    extern __shared__ __align__(16) char sm[];
    uint4* ah_s = (uint4*)(sm + MO_AH);
    uint4* al_s = (uint4*)(sm + MO_AL);
    float* epi  = (float*)(sm + MO_EPI);
    float* ds   = (float*)(sm + MO_DS);
    float* c8s  = (float*)(sm + MO_C8);
    float* als  = (float*)(sm + MO_ALS);

    int tid = threadIdx.x;
    int m0 = blockIdx.x * 64;
    int nt = blockIdx.y, n0 = nt * 128;

    if (tid < 128) { ds[tid] = g_d[n0 + tid]; c8s[tid] = g_c8[n0 + tid]; }
    if (tid < 64)  als[tid] = g_alpha[opt[m0 + tid]];

    // stage A fragments (hi/lo separate, lane-contiguous)
    #pragma unroll
    for (int i = 0; i < 4; i++) {
        int p = tid + i * 256;
        int lane_ = p & 31, s = (p >> 5) & 7, mf = p >> 8;
        int row = m0 + mf * 16 + (lane_ >> 2);
        int k0 = s * 16 + (lane_ & 3) * 2;
        const float* xr = x + (size_t)row * 128;
        float2 xa = *(const float2*)(xr + k0);
        float2 xb = *(const float2*)(xr + 8 * 128 + k0);
        float2 xc = *(const float2*)(xr + k0 + 8);
        float2 xd = *(const float2*)(xr + 8 * 128 + k0 + 8);
        uint4 hi, lo;
        hilo(xa, hi.x, lo.x); hilo(xb, hi.y, lo.y);
        hilo(xc, hi.z, lo.z); hilo(xd, hi.w, lo.w);
        ah_s[p] = hi;
        al_s[p] = lo;
    }
    __syncthreads();

    int wid = tid >> 5, lane = tid & 31;
    int wm = wid & 1, wn = wid >> 1;
    const uint4* bg = g_bfr + nt * 4096 + (wn * 4) * 256 + lane;  // t stride 256, s stride 32

    float acc[2][4][4];
    #pragma unroll
    for (int a_ = 0; a_ < 2; a_++)
        #pragma unroll
        for (int b_ = 0; b_ < 4; b_++)
            #pragma unroll
            for (int c_ = 0; c_ < 4; c_++) acc[a_][b_][c_] = 0.f;

    #pragma unroll
    for (int s = 0; s < 8; s++) {
        uint4 bq0 = bg[0 * 256 + s * 32];
        uint4 bq1 = bg[1 * 256 + s * 32];
        uint4 bq2 = bg[2 * 256 + s * 32];
        uint4 bq3 = bg[3 * 256 + s * 32];
        uint4 ah[2], al[2];
        #pragma unroll
        for (int mt = 0; mt < 2; mt++) {
            int fp = ((wm * 2 + mt) * 8 + s) * 32 + lane;
            ah[mt] = ah_s[fp];
            al[mt] = al_s[fp];
        }
        #pragma unroll
        for (int mt = 0; mt < 2; mt++) {
            mma16816(acc[mt][0], (const uint32_t*)&ah[mt], bq0.x, bq0.y);
            mma16816(acc[mt][0], (const uint32_t*)&ah[mt], bq0.z, bq0.w);
            mma16816(acc[mt][0], (const uint32_t*)&al[mt], bq0.x, bq0.y);
            mma16816(acc[mt][1], (const uint32_t*)&ah[mt], bq1.x, bq1.y);
            mma16816(acc[mt][1], (const uint32_t*)&ah[mt], bq1.z, bq1.w);
            mma16816(acc[mt][1], (const uint32_t*)&al[mt], bq1.x, bq1.y);
            mma16816(acc[mt][2], (const uint32_t*)&ah[mt], bq2.x, bq2.y);
            mma16816(acc[mt][2], (const uint32_t*)&ah[mt], bq2.z, bq2.w);
            mma16816(acc[mt][2], (const uint32_t*)&al[mt], bq2.x, bq2.y);
            mma16816(acc[mt][3], (const uint32_t*)&ah[mt], bq3.x, bq3.y);
            mma16816(acc[mt][3], (const uint32_t*)&ah[mt], bq3.z, bq3.w);
            mma16816(acc[mt][3], (const uint32_t*)&al[mt], bq3.x, bq3.y);
        }
    }

    // --- epilogue: raw accs -> smem (overwrites A frags), coalesced read-back ---
    __syncthreads();
    int g = lane >> 2, tq = lane & 3;
    #pragma unroll
    for (int mt = 0; mt < 2; mt++) {
        int rl = wm * 32 + mt * 16 + g;
        #pragma unroll
        for (int t = 0; t < 4; t++) {
            int nl = wn * 32 + t * 8 + tq * 2;
            float* c = acc[mt][t];
            *(float2*)&epi[rl * 132 + nl]       = make_float2(c[0], c[1]);
            *(float2*)&epi[(rl + 8) * 132 + nl] = make_float2(c[2], c[3]);
        }
    }
    float4 dd = *(const float4*)&ds[lane * 4];
    float4 cc = *(const float4*)&c8s[lane * 4];
    __syncthreads();

    #pragma unroll
    for (int it = 0; it < 8; it++) {
        int row = wid * 8 + it;
        float a = als[row];
        float4 v = *(const float4*)&epi[row * 132 + lane * 4];
        float4 o;
        o.x = fmaf(v.x + dd.x, a, cc.x);
        o.y = fmaf(v.y + dd.y, a, cc.y);
        o.z = fmaf(v.z + dd.z, a, cc.z);
        o.w = fmaf(v.w + dd.w, a, cc.w);
        *(float4*)&out[(size_t)(m0 + row) * 256 + n0 + lane * 4] = o;
    }
}

extern "C" void kernel_launch(void* const* d_in, const int* in_sizes, int n_in,
                              void* d_out, int out_size) {
    const float* x        = (const float*)d_in[0];   // (8192,128)
    const int*   option   = (const int*)  d_in[1];   // (8192,)
    const float* pre_fc_w = (const float*)d_in[2];   // (128,512)
    const float* pre_fc_b = (const float*)d_in[3];   // (512,)
    const float* value_w  = (const float*)d_in[4];   // (512,1024)
    const float* value_b  = (const float*)d_in[5];   // (1024,)
    const float* p_w      = (const float*)d_in[6];   // (16,64)
    const float* p_b      = (const float*)d_in[7];   // (64,)
    float* out = (float*)d_out;                      // (8192,256)

    prep1<<<dim3(17, 16), 256>>>(pre_fc_w, pre_fc_b, value_w, p_w, p_b, value_b);
    main_hmma<<<dim3(128, 2), 256, MSMEM>>>(x, option, out);
}